// round 11
// baseline (speedup 1.0000x reference)
#include <cuda_runtime.h>
#include <math.h>

#define BATCH 128
#define HH 512
#define WW 512
#define HW (HH*WW)
#define W4R (WW/4)       // 128 float4 per image row

// Per-batch compute region: 98 rows x 112 cols (floats), one CTA per batch.
// Seed at local (49, sx), sx in [56,59]. Support after k global iterations
// is the L1-diamond of radius k; threads/warps gate compute on it.
#define RR 98            // region rows
#define RC 112           // region cols (floats)
#define RCF4 (RC/4)      // 28 f4 per row
#define NCOLV 26         // compute f4 columns v = 1..26
#define NGRP 32          // row groups
#define RPG 3            // rows per group: 32*3 = 96 compute rows (1..96)
#define THREADS (NCOLV*NGRP)   // 832 (26 warps)
#define NWARP (THREADS/32)     // 26
#define SMEMB (2*RR*RC*4)      // 87,808 B dynamic
#define FULL 0xffffffffu

__global__ __launch_bounds__(THREADS, 1)
void fused_kernel(const float* __restrict__ floor_,
                  const float* __restrict__ keyloc,
                  const float* __restrict__ locked,
                  const int*   __restrict__ start,
                  const int*   __restrict__ goal,
                  const float* __restrict__ keygate,
                  float*       __restrict__ out)
{
    extern __shared__ float sm[];
    float* R0 = sm;                  // RR*RC
    float* R1 = sm + RR*RC;
    __shared__ float swarp[NWARP];

    const int b  = blockIdx.x;
    const int sr = start[2*b], sc = start[2*b+1];
    const int oy = sr - 49;                 // seed row -> local 49
    const int ox = (sc - 56) & ~3;          // f4-aligned; sx in [56,59]
    const int sx = sc - ox;
    const int tid  = threadIdx.x;
    const int lane = tid & 31;
    const int wid  = tid >> 5;

    // ---- zero both buffers ----
    float4* R04 = (float4*)R0;
    float4* R14 = (float4*)R1;
    const float4 z4 = make_float4(0.f,0.f,0.f,0.f);
    for (int i = tid; i < RR*RCF4; i += THREADS) { R04[i] = z4; R14[i] = z4; }

    // ---- thread -> (f4 column v = 1..26, rows y0..y0+2 in [1,96]) ----
    const int v  = 1 + tid % NCOLV;
    const int g  = tid / NCOLV;
    const int y0 = 1 + g*RPG;
    const float kg = __ldg(keygate);
    const int gx = ox + 4*v;                // multiple of 4
    const bool colIn = ((unsigned)gx < WW);

    // min L1 distance of this 3x4 block to the seed; per-warp min (uniform)
    const int dy_min = max(0, max(y0 - 49, 47 - y0));
    const int dx_min = max(0, max(4*v - sx, sx - (4*v + 3)));
    const int dmin   = dy_min + dx_min;
    int dwarp = dmin;
    #pragma unroll
    for (int off = 16; off > 0; off >>= 1)
        dwarp = min(dwarp, __shfl_xor_sync(FULL, dwarp, off));

    const float4* F4 = (const float4*)(floor_ + (size_t)b*HW);
    const float4* L4 = (const float4*)(locked + (size_t)b*HW);
    const float4* K4 = (const float4*)(keyloc + (size_t)b*HW);
    const int cf4 = gx >> 2;

    // register copy of this thread's 3 rows. Initially zero + seed.
    float4 O0 = z4, O1 = z4, O2 = z4;
    if (sr - oy >= y0 && sr - oy <= y0 + 2 && sx >= 4*v && sx <= 4*v + 3) {
        float* Op = (sr - oy == y0) ? &O0.x : (sr - oy == y0 + 1) ? &O1.x : &O2.x;
        Op[sx - 4*v] = 1.0f;
    }
    __syncthreads();
    if (tid == 0) R0[49*RC + sx] = 1.0f;    // seed (smem)

    float keys = 0.0f;
    float* cur = R0;
    float* nxt = R1;
    __syncthreads();

    #pragma unroll 1
    for (int stage = 0; stage < 3; ++stage) {
        const int kend = 15*(stage + 1);
        // door gate + walk into registers (gated; out-of-image -> 0)
        const float dp = 1.0f / (1.0f + expf(-kg*(keys - 1.0f)));
        float4 Wr[RPG];
        #pragma unroll
        for (int i = 0; i < RPG; ++i) Wr[i] = z4;
        if (dmin <= kend && colIn) {
            #pragma unroll
            for (int i = 0; i < RPG; ++i) {
                int gy = oy + y0 + i;
                if ((unsigned)gy < HH) {
                    size_t off = (size_t)gy*W4R + cf4;
                    float4 f = __ldg(F4 + off), l = __ldg(L4 + off);
                    Wr[i].x = 0.25f*f.x*(1.0f - l.x + l.x*dp);
                    Wr[i].y = 0.25f*f.y*(1.0f - l.y + l.y*dp);
                    Wr[i].z = 0.25f*f.z*(1.0f - l.z + l.z*dp);
                    Wr[i].w = 0.25f*f.w*(1.0f - l.w + l.w*dp);
                }
            }
        }

        // 15 Jacobi iterations; horiz neighbors via shfl, vert via smem
        #pragma unroll 1
        for (int it = 0; it < 15; ++it) {
            const int k = stage*15 + it + 1;
            if (dwarp <= k) {               // warp-uniform gate
                // horizontal neighbor scalars from adjacent lanes' registers
                float Lh0 = __shfl_up_sync(FULL, O0.w, 1);
                float Lh1 = __shfl_up_sync(FULL, O1.w, 1);
                float Lh2 = __shfl_up_sync(FULL, O2.w, 1);
                float Rh0 = __shfl_down_sync(FULL, O0.x, 1);
                float Rh1 = __shfl_down_sync(FULL, O1.x, 1);
                float Rh2 = __shfl_down_sync(FULL, O2.x, 1);
                if (v == 1)          { Lh0 = 0.f; Lh1 = 0.f; Lh2 = 0.f; }
                else if (lane == 0)  { Lh0 = cur[(y0  )*RC + 4*v - 1];
                                       Lh1 = cur[(y0+1)*RC + 4*v - 1];
                                       Lh2 = cur[(y0+2)*RC + 4*v - 1]; }
                if (v == NCOLV)      { Rh0 = 0.f; Rh1 = 0.f; Rh2 = 0.f; }
                else if (lane == 31) { Rh0 = cur[(y0  )*RC + 4*v + 4];
                                       Rh1 = cur[(y0+1)*RC + 4*v + 4];
                                       Rh2 = cur[(y0+2)*RC + 4*v + 4]; }
                if (dmin <= k) {
                    const float4* c4 = (const float4*)cur;
                    float4* n4 = (float4*)nxt;
                    float4 U = c4[(y0-1)*RCF4 + v];
                    float4 D = c4[(y0+3)*RCF4 + v];
                    // boundary rows first (consumers only need these), then mid
                    float4 N0, N2, N1;
                    N0.x = fminf(fmaf((U.x +O1.x)+(Lh0 +O0.y), Wr[0].x, O0.x), 1.0f);
                    N0.y = fminf(fmaf((U.y +O1.y)+(O0.x+O0.z), Wr[0].y, O0.y), 1.0f);
                    N0.z = fminf(fmaf((U.z +O1.z)+(O0.y+O0.w), Wr[0].z, O0.z), 1.0f);
                    N0.w = fminf(fmaf((U.w +O1.w)+(O0.z+Rh0 ), Wr[0].w, O0.w), 1.0f);
                    N2.x = fminf(fmaf((O1.x+D.x )+(Lh2 +O2.y), Wr[2].x, O2.x), 1.0f);
                    N2.y = fminf(fmaf((O1.y+D.y )+(O2.x+O2.z), Wr[2].y, O2.y), 1.0f);
                    N2.z = fminf(fmaf((O1.z+D.z )+(O2.y+O2.w), Wr[2].z, O2.z), 1.0f);
                    N2.w = fminf(fmaf((O1.w+D.w )+(O2.z+Rh2 ), Wr[2].w, O2.w), 1.0f);
                    n4[(y0  )*RCF4 + v] = N0;
                    n4[(y0+2)*RCF4 + v] = N2;
                    N1.x = fminf(fmaf((O0.x+O2.x)+(Lh1 +O1.y), Wr[1].x, O1.x), 1.0f);
                    N1.y = fminf(fmaf((O0.y+O2.y)+(O1.x+O1.z), Wr[1].y, O1.y), 1.0f);
                    N1.z = fminf(fmaf((O0.z+O2.z)+(O1.y+O1.w), Wr[1].z, O1.z), 1.0f);
                    N1.w = fminf(fmaf((O0.w+O2.w)+(O1.z+Rh1 ), Wr[1].w, O1.w), 1.0f);
                    n4[(y0+1)*RCF4 + v] = N1;
                    O0 = N0; O1 = N1; O2 = N2;
                }
            }
            __syncthreads();
            float* t = cur; cur = nxt; nxt = t;
        }

        // fused key reduction (stage 2's keys are dead code in the reference)
        if (stage < 2) {
            float acc = 0.0f;
            if (dmin <= kend && colIn) {        // R==0 beyond radius kend
                #pragma unroll
                for (int i = 0; i < RPG; ++i) {
                    int gy = oy + y0 + i;
                    if ((unsigned)gy < HH) {
                        float4 r = (i == 0) ? O0 : (i == 1) ? O1 : O2;
                        float4 kk = __ldg(K4 + (size_t)gy*W4R + cf4);
                        acc += (r.x*kk.x + r.y*kk.y) + (r.z*kk.z + r.w*kk.w);
                    }
                }
            }
            #pragma unroll
            for (int off = 16; off > 0; off >>= 1)
                acc += __shfl_down_sync(FULL, acc, off);
            if (lane == 0) swarp[wid] = acc;
            __syncthreads();
            float s = 0.0f;
            #pragma unroll
            for (int w = 0; w < NWARP; ++w) s += swarp[w];
            keys += s;                          // identical in every thread
            // no barrier needed: swarp next written >=15 barriers from now
        }
    }

    // gather: out[b] = R at clipped goal (0 outside region == true value)
    if (tid == 0) {
        int gr = min(max(goal[2*b],   0), HH-1);
        int gc = min(max(goal[2*b+1], 0), WW-1);
        int ly = gr - oy, lx = gc - ox;
        float val = 0.0f;
        if ((unsigned)ly < RR && (unsigned)lx < RC) val = cur[ly*RC + lx];
        out[b] = val;
    }
}

// ---------------------------------------------------------------
extern "C" void kernel_launch(void* const* d_in, const int* in_sizes, int n_in,
                              void* d_out, int out_size) {
    const float* floor_  = (const float*)d_in[0];
    const float* keyloc  = (const float*)d_in[1];
    const float* locked  = (const float*)d_in[2];
    const int*   start   = (const int*)  d_in[3];
    const int*   goal    = (const int*)  d_in[4];
    const float* keygate = (const float*)d_in[5];
    float* out = (float*)d_out;

    cudaFuncSetAttribute(fused_kernel,
                         cudaFuncAttributeMaxDynamicSharedMemorySize, SMEMB);
    fused_kernel<<<BATCH, THREADS, SMEMB>>>(floor_, keyloc, locked,
                                            start, goal, keygate, out);
}

// round 12
// speedup vs baseline: 1.4985x; 1.4985x over previous
#include <cuda_runtime.h>
#include <math.h>

#define BATCH 128
#define HH 512
#define WW 512
#define HW (HH*WW)
#define W4R (WW/4)       // 128 float4 per image row

// Per-batch compute region: 98 rows x 112 cols (floats), one CTA per batch.
// Seed at local (49, sx), sx in [56,59]. Support after k global iterations
// is the L1-diamond of radius k; threads gate compute on it.
#define RR 98            // region rows
#define RC 112           // region cols (floats)
#define RCF4 (RC/4)      // 28 f4 per row
#define NCOLV 26         // compute f4 columns v = 1..26
#define NGRP 32          // row groups
#define RPG 3            // rows per group: 32*3 = 96 compute rows (1..96)
#define THREADS (NCOLV*NGRP)   // 832 (26 warps)
#define NWARP (THREADS/32)     // 26
#define SMEMB (2*RR*RC*4)      // 87,808 B dynamic
#define FULL 0xffffffffu

__global__ __launch_bounds__(THREADS, 1)
void fused_kernel(const float* __restrict__ floor_,
                  const float* __restrict__ keyloc,
                  const float* __restrict__ locked,
                  const int*   __restrict__ start,
                  const int*   __restrict__ goal,
                  const float* __restrict__ keygate,
                  float*       __restrict__ out)
{
    extern __shared__ float sm[];
    float* R0 = sm;                  // RR*RC
    float* R1 = sm + RR*RC;
    __shared__ float swarp[NWARP];

    const int b  = blockIdx.x;
    const int sr = start[2*b], sc = start[2*b+1];
    const int oy = sr - 49;                 // seed row -> local 49
    const int ox = (sc - 56) & ~3;          // f4-aligned; sx in [56,59]
    const int sx = sc - ox;
    const int tid  = threadIdx.x;
    const int lane = tid & 31;
    const int wid  = tid >> 5;

    // ---- zero both buffers ----
    float4* R04 = (float4*)R0;
    float4* R14 = (float4*)R1;
    const float4 z4 = make_float4(0.f,0.f,0.f,0.f);
    for (int i = tid; i < RR*RCF4; i += THREADS) { R04[i] = z4; R14[i] = z4; }
    __syncthreads();
    if (tid == 0) R0[49*RC + sx] = 1.0f;    // seed (smem)

    // ---- thread -> (f4 column v = 1..26, rows y0..y0+2 in [1,96]) ----
    const int v  = 1 + tid % NCOLV;
    const int g  = tid / NCOLV;
    const int y0 = 1 + g*RPG;
    const float kg = __ldg(keygate);
    const int gx = ox + 4*v;                // multiple of 4
    const bool colIn = ((unsigned)gx < WW);

    // min L1 distance from this thread's 3x4 block to the seed (constant)
    const int dy_min = max(0, max(y0 - 49, 47 - y0));
    const int dx_min = max(0, max(4*v - sx, sx - (4*v + 3)));
    const int dmin   = dy_min + dx_min;

    const float4* F4 = (const float4*)(floor_ + (size_t)b*HW);
    const float4* L4 = (const float4*)(locked + (size_t)b*HW);
    const float4* K4 = (const float4*)(keyloc + (size_t)b*HW);
    const int cf4 = gx >> 2;

    // thread-local base pointers (16B-aligned) -> all smem ops use const imms
    float* pA = R0 + y0*RC + 4*v;
    float* pB = R1 + y0*RC + 4*v;
    float* curBuf = R0;              // whole-buffer pointer for the gather

    // register copy of this thread's 3 rows (state). Initially zero + seed.
    float4 O0 = z4, O1 = z4, O2 = z4;
    if (sr - oy >= y0 && sr - oy <= y0 + 2 && sx >= 4*v && sx <= 4*v + 3) {
        float* Op = (sr - oy == y0) ? &O0.x : (sr - oy == y0 + 1) ? &O1.x : &O2.x;
        Op[sx - 4*v] = 1.0f;
    }

    float keys = 0.0f;
    __syncthreads();

    #pragma unroll 1
    for (int stage = 0; stage < 3; ++stage) {
        const int kend = 15*(stage + 1);
        const int drem = dmin - 15*stage;   // gate: compute iff drem <= it+1
        // door gate + walk into registers (gated; out-of-image -> 0)
        const float dp = 1.0f / (1.0f + expf(-kg*(keys - 1.0f)));
        float4 Wr[RPG];
        #pragma unroll
        for (int i = 0; i < RPG; ++i) Wr[i] = z4;
        if (dmin <= kend && colIn) {
            #pragma unroll
            for (int i = 0; i < RPG; ++i) {
                int gy = oy + y0 + i;
                if ((unsigned)gy < HH) {
                    size_t off = (size_t)gy*W4R + cf4;
                    float4 f = __ldg(F4 + off), l = __ldg(L4 + off);
                    Wr[i].x = 0.25f*f.x*(1.0f - l.x + l.x*dp);
                    Wr[i].y = 0.25f*f.y*(1.0f - l.y + l.y*dp);
                    Wr[i].z = 0.25f*f.z*(1.0f - l.z + l.z*dp);
                    Wr[i].w = 0.25f*f.w*(1.0f - l.w + l.w*dp);
                }
            }
        }

        // 15 Jacobi iterations, fully unrolled; buffer parity compile-time.
        #pragma unroll
        for (int it = 0; it < 15; ++it) {
            float* cu = (it & 1) ? pB : pA;
            float* nx = (it & 1) ? pA : pB;
            if (drem <= it + 1) {
                float4 U = *(const float4*)(cu - RC);
                float4 D = *(const float4*)(cu + 3*RC);
                float L0 = cu[-1],      Rh0 = cu[4];
                float L1 = cu[RC-1],    Rh1 = cu[RC+4];
                float L2 = cu[2*RC-1],  Rh2 = cu[2*RC+4];
                float4 N0, N1, N2;
                N0.x = fminf(fmaf((U.x +O1.x)+(L0  +O0.y), Wr[0].x, O0.x), 1.0f);
                N0.y = fminf(fmaf((U.y +O1.y)+(O0.x+O0.z), Wr[0].y, O0.y), 1.0f);
                N0.z = fminf(fmaf((U.z +O1.z)+(O0.y+O0.w), Wr[0].z, O0.z), 1.0f);
                N0.w = fminf(fmaf((U.w +O1.w)+(O0.z+Rh0 ), Wr[0].w, O0.w), 1.0f);
                N2.x = fminf(fmaf((O1.x+D.x )+(L2  +O2.y), Wr[2].x, O2.x), 1.0f);
                N2.y = fminf(fmaf((O1.y+D.y )+(O2.x+O2.z), Wr[2].y, O2.y), 1.0f);
                N2.z = fminf(fmaf((O1.z+D.z )+(O2.y+O2.w), Wr[2].z, O2.z), 1.0f);
                N2.w = fminf(fmaf((O1.w+D.w )+(O2.z+Rh2 ), Wr[2].w, O2.w), 1.0f);
                *(float4*)(nx)        = N0;   // boundary rows first
                *(float4*)(nx + 2*RC) = N2;
                N1.x = fminf(fmaf((O0.x+O2.x)+(L1  +O1.y), Wr[1].x, O1.x), 1.0f);
                N1.y = fminf(fmaf((O0.y+O2.y)+(O1.x+O1.z), Wr[1].y, O1.y), 1.0f);
                N1.z = fminf(fmaf((O0.z+O2.z)+(O1.y+O1.w), Wr[1].z, O1.z), 1.0f);
                N1.w = fminf(fmaf((O0.w+O2.w)+(O1.z+Rh1 ), Wr[1].w, O1.w), 1.0f);
                *(float4*)(nx + RC)   = N1;
                O0 = N0; O1 = N1; O2 = N2;
            }
            __syncthreads();
        }
        // 15 iterations (odd) -> state ended in the B-parity buffer; swap.
        { float* t = pA; pA = pB; pB = t; }
        curBuf = (curBuf == R0) ? R1 : R0;

        // fused key reduction (stage 2's keys are dead code in the reference)
        if (stage < 2) {
            float acc = 0.0f;
            if (dmin <= kend && colIn) {        // R==0 beyond radius kend
                #pragma unroll
                for (int i = 0; i < RPG; ++i) {
                    int gy = oy + y0 + i;
                    if ((unsigned)gy < HH) {
                        float4 r = (i == 0) ? O0 : (i == 1) ? O1 : O2;
                        float4 kk = __ldg(K4 + (size_t)gy*W4R + cf4);
                        acc += (r.x*kk.x + r.y*kk.y) + (r.z*kk.z + r.w*kk.w);
                    }
                }
            }
            #pragma unroll
            for (int off = 16; off > 0; off >>= 1)
                acc += __shfl_down_sync(FULL, acc, off);
            if (lane == 0) swarp[wid] = acc;
            __syncthreads();
            float s = 0.0f;
            #pragma unroll
            for (int w = 0; w < NWARP; ++w) s += swarp[w];
            keys += s;                          // identical in every thread
            // no barrier needed: swarp next written >=15 barriers from now
        }
    }

    // gather: out[b] = R at clipped goal (0 outside region == true value)
    if (tid == 0) {
        int gr = min(max(goal[2*b],   0), HH-1);
        int gc = min(max(goal[2*b+1], 0), WW-1);
        int ly = gr - oy, lx = gc - ox;
        float val = 0.0f;
        if ((unsigned)ly < RR && (unsigned)lx < RC) val = curBuf[ly*RC + lx];
        out[b] = val;
    }
}

// ---------------------------------------------------------------
extern "C" void kernel_launch(void* const* d_in, const int* in_sizes, int n_in,
                              void* d_out, int out_size) {
    const float* floor_  = (const float*)d_in[0];
    const float* keyloc  = (const float*)d_in[1];
    const float* locked  = (const float*)d_in[2];
    const int*   start   = (const int*)  d_in[3];
    const int*   goal    = (const int*)  d_in[4];
    const float* keygate = (const float*)d_in[5];
    float* out = (float*)d_out;

    cudaFuncSetAttribute(fused_kernel,
                         cudaFuncAttributeMaxDynamicSharedMemorySize, SMEMB);
    fused_kernel<<<BATCH, THREADS, SMEMB>>>(floor_, keyloc, locked,
                                            start, goal, keygate, out);
}